// round 1
// baseline (speedup 1.0000x reference)
#include <cuda_runtime.h>

#define DIM 160
#define NB  2

// Scratch (static device globals — no allocation in kernel_launch).
// bufA: max = 5 fields * 2 * 160*160*71 = 18,176,000 floats (~72.7 MB)
// bufB: max = 5 fields * 2 * 160*71*71  =  8,065,600 floats (~32.3 MB)
__device__ float g_bufA[18176000];
__device__ float g_bufB[8065600];
__device__ float g_partials[4096];
__device__ float g_contrib[3];

// Pass 1: reduce innermost dim z2 (contiguous). Computes all 5 field products
// (x, y, x^2, y^2, x*y) while reading input/target exactly once.
// out layout: [field][b][z0][z1][o2], o2 fastest.
__global__ void pass1_kernel(const float* __restrict__ x,
                             const float* __restrict__ y,
                             int k, int s, int O, int N1) {
    int idx = blockIdx.x * blockDim.x + threadIdx.x;
    if (idx >= N1) return;
    int o2 = idx % O;
    int r  = idx / O;
    int z1 = r % DIM; r /= DIM;
    int z0 = r % DIM;
    int b  = r / DIM;
    int base = (((b * DIM + z0) * DIM + z1) * DIM) + o2 * s;
    const float* xp = x + base;
    const float* yp = y + base;
    float sx = 0.f, sy = 0.f, sxx = 0.f, syy = 0.f, sxy = 0.f;
#pragma unroll 4
    for (int t = 0; t < k; t++) {
        float xv = xp[2 * t];
        float yv = yp[2 * t];
        sx  += xv;
        sy  += yv;
        sxx += xv * xv;
        syy += yv * yv;
        sxy += xv * yv;
    }
    g_bufA[0 * N1 + idx] = sx;
    g_bufA[1 * N1 + idx] = sy;
    g_bufA[2 * N1 + idx] = sxx;
    g_bufA[3 * N1 + idx] = syy;
    g_bufA[4 * N1 + idx] = sxy;
}

// Pass 2: reduce z1. in [f][b][z0][z1=160][O] -> out [f][b][z0][o1][o2].
// threadIdx.x maps to o2 (fast) -> each tap read is a coalesced row.
__global__ void pass2_kernel(int k, int s, int O, int N1, int N2) {
    int idx = blockIdx.x * blockDim.x + threadIdx.x;
    if (idx >= N2) return;
    int o2 = idx % O;
    int r  = idx / O;
    int o1 = r % O;  r /= O;
    int z0 = r % DIM;
    int b  = r / DIM;
    int inbase = ((b * DIM + z0) * DIM + o1 * s) * O + o2;
    int tapstride = 2 * O;
#pragma unroll
    for (int f = 0; f < 5; f++) {
        const float* p = g_bufA + f * N1 + inbase;
        float acc = 0.f;
#pragma unroll 4
        for (int t = 0; t < k; t++) acc += p[t * tapstride];
        g_bufB[f * N2 + idx] = acc;
    }
}

// Pass 3: reduce z0. in [f][b][z0=160][o1][o2] -> out [f][b][o0][o1][o2].
// Output written back into g_bufA (pass1 data no longer needed).
__global__ void pass3_kernel(int k, int s, int O, int N2, int N3) {
    int idx = blockIdx.x * blockDim.x + threadIdx.x;
    if (idx >= N3) return;
    int o2 = idx % O;
    int r  = idx / O;
    int o1 = r % O;  r /= O;
    int o0 = r % O;
    int b  = r / O;
    int inbase = ((b * DIM + o0 * s) * O + o1) * O + o2;
    int tapstride = 2 * O * O;
#pragma unroll
    for (int f = 0; f < 5; f++) {
        const float* p = g_bufB + f * N2 + inbase;
        float acc = 0.f;
#pragma unroll 4
        for (int t = 0; t < k; t++) acc += p[t * tapstride];
        g_bufA[f * N3 + idx] = acc;
    }
}

// Pass 4: per-voxel LNCC + deterministic block reduction to partials.
__global__ void pass4_kernel(int N3, float numel) {
    __shared__ float sh[256];
    int idx = blockIdx.x * blockDim.x + threadIdx.x;
    float v = 0.f;
    if (idx < N3) {
        float sx  = g_bufA[0 * N3 + idx];
        float sy  = g_bufA[1 * N3 + idx];
        float sxx = g_bufA[2 * N3 + idx];
        float syy = g_bufA[3 * N3 + idx];
        float sxy = g_bufA[4 * N3 + idx];
        float xm = sx / numel;
        float ym = sy / numel;
        float cross = sxy - ym * sx - xm * sy + ym * xm * numel;
        float xvar  = sxx - 2.f * xm * sx + xm * xm * numel;
        float yvar  = syy - 2.f * ym * sy + ym * ym * numel;
        v = cross * cross / (xvar * yvar + 1e-5f);
    }
    sh[threadIdx.x] = v;
    __syncthreads();
#pragma unroll
    for (int st = 128; st > 0; st >>= 1) {
        if (threadIdx.x < st) sh[threadIdx.x] += sh[threadIdx.x + st];
        __syncthreads();
    }
    if (threadIdx.x == 0) g_partials[blockIdx.x] = sh[0];
}

// Single-block, fixed-order final reduction for one scale -> contribution.
__global__ void finalize_kernel(int nblocks, int N3, float w, int scaleIdx) {
    __shared__ float sh[256];
    float a = 0.f;
    for (int i = threadIdx.x; i < nblocks; i += 256) a += g_partials[i];
    sh[threadIdx.x] = a;
    __syncthreads();
#pragma unroll
    for (int st = 128; st > 0; st >>= 1) {
        if (threadIdx.x < st) sh[threadIdx.x] += sh[threadIdx.x + st];
        __syncthreads();
    }
    if (threadIdx.x == 0)
        g_contrib[scaleIdx] = (1.0f - sh[0] / (float)N3) * w;
}

__global__ void combine_kernel(float* __restrict__ out) {
    out[0] = g_contrib[0] + g_contrib[1] + g_contrib[2];
}

extern "C" void kernel_launch(void* const* d_in, const int* in_sizes, int n_in,
                              void* d_out, int out_size) {
    const float* x = (const float*)d_in[0];   // input
    const float* y = (const float*)d_in[1];   // target
    float* out = (float*)d_out;

    // scale config for img_sz = 160 (>128): scales, strides, dilation=2
    const int   ks[3] = {10, 20, 40};
    const int   ss[3] = {2, 5, 10};
    const int   Os[3] = {71, 25, 9};   // (160 - 2*(k-1) - 1)/s + 1
    const float wsc[3] = {0.1f, 0.3f, 0.6f};

    for (int sc = 0; sc < 3; sc++) {
        int k = ks[sc], s = ss[sc], O = Os[sc];
        int N1 = NB * DIM * DIM * O;
        int N2 = NB * DIM * O * O;
        int N3 = NB * O * O * O;
        pass1_kernel<<<(N1 + 255) / 256, 256>>>(x, y, k, s, O, N1);
        pass2_kernel<<<(N2 + 255) / 256, 256>>>(k, s, O, N1, N2);
        pass3_kernel<<<(N3 + 255) / 256, 256>>>(k, s, O, N2, N3);
        int nb4 = (N3 + 255) / 256;
        float numel = (float)k * (float)k * (float)k;
        pass4_kernel<<<nb4, 256>>>(N3, numel);
        finalize_kernel<<<1, 256>>>(nb4, N3, wsc[sc], sc);
    }
    combine_kernel<<<1, 1>>>(out);
}

// round 2
// speedup vs baseline: 1.2051x; 1.2051x over previous
#include <cuda_runtime.h>

#define DIM 160
#define NB  2

// ---- problem constants (img 160^3, >128 branch) ----
// scale0: k=10 s=2  O=71   scale1: k=20 s=5 O=25   scale2: k=40 s=10 O=9
#define O0 71
#define O1 25
#define O2 9
#define N1_0 (NB*DIM*DIM*O0)   // 3,635,200
#define N1_1 (NB*DIM*DIM*O1)   // 1,280,000
#define N1_2 (NB*DIM*DIM*O2)   //   460,800
#define OFFA0 0
#define OFFA1 (5*N1_0)         // 18,176,000
#define OFFA2 (OFFA1 + 5*N1_1) // 24,576,000

#define N2_0 (NB*DIM*O0*O0)    // 1,613,120
#define N2_1 (NB*DIM*O1*O1)    //   200,000
#define N2_2 (NB*DIM*O2*O2)    //    25,920

#define N3_0 (NB*O0*O0*O0)     //   715,822
#define N3_1 (NB*O1*O1*O1)     //    31,250
#define N3_2 (NB*O2*O2*O2)     //     1,458

#define PBASE0 0
#define PBASE1 2800
#define PBASE2 2928

// Scratch (static device globals; no allocation in kernel_launch).
__device__ float g_bufA[OFFA2 + 5*N1_2];   // ~107.5 MB
__device__ float g_bufB[5*N2_0];           // ~32.3 MB (reused per scale)
__device__ float g_partials[4096];

// ---------------------------------------------------------------------------
// Pass 1 (all scales fused): one block per (b,z0,z1) row. Reads x,y ONCE,
// stages the 5 products in smem, then computes every scale's z2-window sums.
// Output layout per scale: [field][row][o2], row = ((b*DIM+z0)*DIM+z1).
// ---------------------------------------------------------------------------
__global__ __launch_bounds__(160) void pass1_all(const float* __restrict__ x,
                                                 const float* __restrict__ y) {
    __shared__ float sp[5][DIM];
    int row  = blockIdx.x;           // 0 .. NB*DIM*DIM-1
    int t    = threadIdx.x;          // 0..159
    int base = row * DIM + t;
    float xv = x[base];
    float yv = y[base];
    sp[0][t] = xv;
    sp[1][t] = yv;
    sp[2][t] = xv * xv;
    sp[3][t] = yv * yv;
    sp[4][t] = xv * yv;
    __syncthreads();

    int k, s, O, offA, N1, o2;
    if (t < O0)            { k = 10; s = 2;  O = O0; offA = OFFA0; N1 = N1_0; o2 = t; }
    else if (t < O0+O1)    { k = 20; s = 5;  O = O1; offA = OFFA1; N1 = N1_1; o2 = t - O0; }
    else if (t < O0+O1+O2) { k = 40; s = 10; O = O2; offA = OFFA2; N1 = N1_2; o2 = t - O0 - O1; }
    else return;

    float a0 = 0.f, a1 = 0.f, a2 = 0.f, a3 = 0.f, a4 = 0.f;
    int z = o2 * s;
    for (int tap = 0; tap < k; tap++, z += 2) {
        a0 += sp[0][z];
        a1 += sp[1][z];
        a2 += sp[2][z];
        a3 += sp[3][z];
        a4 += sp[4][z];
    }
    int w = offA + row * O + o2;
    g_bufA[w]          = a0;
    g_bufA[w + 1*N1]   = a1;
    g_bufA[w + 2*N1]   = a2;
    g_bufA[w + 3*N1]   = a3;
    g_bufA[w + 4*N1]   = a4;
}

// ---------------------------------------------------------------------------
// Pass 2: reduce z1. in [f][b][z0][z1=160][O] -> out [f][b][z0][o1][o2].
// ---------------------------------------------------------------------------
template<int K, int S, int O, int OFFA, int N1, int N2>
__global__ void pass2_k() {
    int idx = blockIdx.x * blockDim.x + threadIdx.x;
    if (idx >= N2) return;
    int o2 = idx % O;
    int r  = idx / O;
    int o1 = r % O;  r /= O;
    int z0 = r % DIM;
    int b  = r / DIM;
    int inbase = ((b * DIM + z0) * DIM + o1 * S) * O + o2;
    const int tapstride = 2 * O;
#pragma unroll
    for (int f = 0; f < 5; f++) {
        const float* p = g_bufA + OFFA + f * N1 + inbase;
        float acc = 0.f;
#pragma unroll 10
        for (int t = 0; t < K; t++) acc += p[t * tapstride];
        g_bufB[f * N2 + idx] = acc;
    }
}

// ---------------------------------------------------------------------------
// Pass 3+4 fused: reduce z0, evaluate LNCC, block-reduce (deterministic).
// in bufB [f][b][z0=160][o1][o2]; partials -> g_partials[pbase + blk].
// ---------------------------------------------------------------------------
template<int K, int S, int O, int N2, int N3, int PBASE>
__global__ void pass34_k(float numel) {
    int idx = blockIdx.x * blockDim.x + threadIdx.x;
    float v = 0.f;
    if (idx < N3) {
        int o2 = idx % O;
        int r  = idx / O;
        int o1 = r % O;  r /= O;
        int o0 = r % O;
        int b  = r / O;
        int inbase = ((b * DIM + o0 * S) * O + o1) * O + o2;
        const int tapstride = 2 * O * O;
        float acc[5];
#pragma unroll
        for (int f = 0; f < 5; f++) {
            const float* p = g_bufB + f * N2 + inbase;
            float a = 0.f;
#pragma unroll 10
            for (int t = 0; t < K; t++) a += p[t * tapstride];
            acc[f] = a;
        }
        float xm = acc[0] / numel;
        float ym = acc[1] / numel;
        float cross = acc[4] - ym * acc[0] - xm * acc[1] + ym * xm * numel;
        float xvar  = acc[2] - 2.f * xm * acc[0] + xm * xm * numel;
        float yvar  = acc[3] - 2.f * ym * acc[1] + ym * ym * numel;
        v = cross * cross / (xvar * yvar + 1e-5f);
    }
    // deterministic block reduction: warp shuffle + smem tree
    __shared__ float wsum[8];
    int lane = threadIdx.x & 31;
    int wid  = threadIdx.x >> 5;
#pragma unroll
    for (int o = 16; o > 0; o >>= 1) v += __shfl_down_sync(0xffffffffu, v, o);
    if (lane == 0) wsum[wid] = v;
    __syncthreads();
    if (wid == 0) {
        v = (lane < 8) ? wsum[lane] : 0.f;
#pragma unroll
        for (int o = 4; o > 0; o >>= 1) v += __shfl_down_sync(0xffffffffu, v, o);
        if (lane == 0) g_partials[PBASE + blockIdx.x] = v;
    }
}

// ---------------------------------------------------------------------------
// Final combine: deterministically reduce each scale's partials, apply
// (1 - mean)*w, sum the three contributions, write the scalar.
// ---------------------------------------------------------------------------
__global__ void final_combine(float* __restrict__ out) {
    __shared__ float sh[256];
    const int   pbase[3] = {PBASE0, PBASE1, PBASE2};
    const int   nblk[3]  = {(N3_0 + 255) / 256, (N3_1 + 255) / 256, (N3_2 + 255) / 256};
    const float ninv[3]  = {1.0f / N3_0, 1.0f / N3_1, 1.0f / N3_2};
    const float wsc[3]   = {0.1f, 0.3f, 0.6f};
    float total = 0.f;
    for (int sc = 0; sc < 3; sc++) {
        float a = 0.f;
        for (int i = threadIdx.x; i < nblk[sc]; i += 256) a += g_partials[pbase[sc] + i];
        sh[threadIdx.x] = a;
        __syncthreads();
#pragma unroll
        for (int st = 128; st > 0; st >>= 1) {
            if (threadIdx.x < st) sh[threadIdx.x] += sh[threadIdx.x + st];
            __syncthreads();
        }
        if (threadIdx.x == 0) total += (1.0f - sh[0] * ninv[sc]) * wsc[sc];
        __syncthreads();
    }
    if (threadIdx.x == 0) out[0] = total;
}

extern "C" void kernel_launch(void* const* d_in, const int* in_sizes, int n_in,
                              void* d_out, int out_size) {
    const float* x = (const float*)d_in[0];
    const float* y = (const float*)d_in[1];
    float* out = (float*)d_out;

    pass1_all<<<NB * DIM * DIM, 160>>>(x, y);

    // scale 0: k=10, s=2, O=71
    pass2_k<10, 2, O0, OFFA0, N1_0, N2_0><<<(N2_0 + 255) / 256, 256>>>();
    pass34_k<10, 2, O0, N2_0, N3_0, PBASE0><<<(N3_0 + 255) / 256, 256>>>(1000.0f);

    // scale 1: k=20, s=5, O=25
    pass2_k<20, 5, O1, OFFA1, N1_1, N2_1><<<(N2_1 + 255) / 256, 256>>>();
    pass34_k<20, 5, O1, N2_1, N3_1, PBASE1><<<(N3_1 + 255) / 256, 256>>>(8000.0f);

    // scale 2: k=40, s=10, O=9
    pass2_k<40, 10, O2, OFFA2, N1_2, N2_2><<<(N2_2 + 255) / 256, 256>>>();
    pass34_k<40, 10, O2, N2_2, N3_2, PBASE2><<<(N3_2 + 255) / 256, 256>>>(64000.0f);

    final_combine<<<1, 256>>>(out);
}

// round 3
// speedup vs baseline: 2.2916x; 1.9015x over previous
#include <cuda_runtime.h>

#define DIM 160
#define NB  2

// ---- problem constants (img 160^3, >128 branch) ----
// scale0: k=10 s=2  O=71   scale1: k=20 s=5 O=25   scale2: k=40 s=10 O=9
// Parity pruning: scale0 taps touch only even z (NZ=80, z=2*zi, tap idx o+t)
//                 scale1 taps touch mixed parity (NZ=160, z=zi, tap idx 5*o+2t)
//                 scale2 taps touch only even z (NZ=80, z=2*zi, tap idx 5*o+t)
#define O0 71
#define O1 25
#define O2 9
#define NZ0 80
#define NZ1c 160
#define NZ2 80

#define FS0 (NB*NZ0*O0*O0)     // 806,560 per field
#define FS1 (NB*NZ1c*O1*O1)    // 200,000
#define FS2 (NB*NZ2*O2*O2)     //  12,960
#define OFF0 0
#define OFF1 (5*FS0)           // 4,032,800
#define OFF2 (OFF1 + 5*FS1)    // 5,032,800

#define N3_0 (NB*O0*O0*O0)     // 715,822
#define N3_1 (NB*O1*O1*O1)     //  31,250
#define N3_2 (NB*O2*O2*O2)     //   1,458

#define PBASE0 0
#define PBASE1 2800
#define PBASE2 2928

__device__ float g_bufB[OFF2 + 5*FS2];   // ~20.4 MB
__device__ float g_partials[4096];

// ---------------------------------------------------------------------------
// fused12: pass1+pass2 for one scale. One block per (b, z0i) plane.
// Phase 1: 8 warps independently stream needed z1 rows; each warp loads its
//          row (coalesced), computes 5 field products + z2-window sums into
//          smem zwin[NZ][5][O].
// Phase 2: reduce z1 out of smem, write [f][b][z0i][o1][o2] to global.
// Template: K taps, S z2-stride, O outputs, NZ z-planes kept, ZS z compaction
//           (z = ZS*zi), tap plane idx = B0*o + TS*t, OFF/FS output layout.
// ---------------------------------------------------------------------------
template<int K, int S, int O, int NZ, int ZS, int B0, int TS, int OFF, int FS>
__global__ __launch_bounds__(256) void fused12(const float* __restrict__ x,
                                               const float* __restrict__ y) {
    extern __shared__ float sm[];
    float* zwin = sm;                       // [NZ][5][O]
    float* xb   = sm + NZ * 5 * O;          // [8][DIM]
    float* yb   = xb + 8 * DIM;             // [8][DIM]

    int z0i = blockIdx.x % NZ;
    int b   = blockIdx.x / NZ;
    int z0  = ZS * z0i;
    int w    = threadIdx.x >> 5;
    int lane = threadIdx.x & 31;
    float* xrow = xb + w * DIM;
    float* yrow = yb + w * DIM;

    const int ROWS = NZ / 8;
    for (int r = 0; r < ROWS; r++) {
        int z1i = r * 8 + w;
        int z1  = ZS * z1i;
        const float* xr = x + ((size_t)(b * DIM + z0) * DIM + z1) * DIM;
        const float* yr = y + ((size_t)(b * DIM + z0) * DIM + z1) * DIM;
#pragma unroll
        for (int i = lane; i < DIM; i += 32) {
            xrow[i] = xr[i];
            yrow[i] = yr[i];
        }
        __syncwarp();
        for (int o2 = lane; o2 < O; o2 += 32) {
            float a0 = 0.f, a1 = 0.f, a2 = 0.f, a3 = 0.f, a4 = 0.f;
#pragma unroll
            for (int t = 0; t < K; t++) {
                int z2 = o2 * S + 2 * t;
                float xv = xrow[z2];
                float yv = yrow[z2];
                a0 += xv;
                a1 += yv;
                a2 += xv * xv;
                a3 += yv * yv;
                a4 += xv * yv;
            }
            float* zw = zwin + (size_t)z1i * 5 * O + o2;
            zw[0 * O] = a0;
            zw[1 * O] = a1;
            zw[2 * O] = a2;
            zw[3 * O] = a3;
            zw[4 * O] = a4;
        }
        __syncwarp();
    }
    __syncthreads();

    const int ITEMS = 5 * O * O;
    for (int item = threadIdx.x; item < ITEMS; item += 256) {
        int f   = item / (O * O);
        int rem = item % (O * O);
        int o1  = rem / O;
        int o2  = rem % O;
        float acc = 0.f;
#pragma unroll
        for (int t = 0; t < K; t++)
            acc += zwin[(size_t)(B0 * o1 + TS * t) * 5 * O + f * O + o2];
        g_bufB[OFF + f * FS + (((b * NZ) + z0i) * O + o1) * O + o2] = acc;
    }
}

// ---------------------------------------------------------------------------
// pass3+4 fused: reduce z0 (compacted plane index), evaluate LNCC,
// deterministic block reduction into g_partials[PBASE + blk].
// ---------------------------------------------------------------------------
template<int K, int O, int NZ, int B0, int TS, int OFF, int FS, int N3, int PBASE>
__global__ void pass34_k() {
    const float numel = (float)K * (float)K * (float)K;
    int idx = blockIdx.x * blockDim.x + threadIdx.x;
    float v = 0.f;
    if (idx < N3) {
        int o2 = idx % O;
        int r  = idx / O;
        int o1 = r % O;  r /= O;
        int o0 = r % O;
        int b  = r / O;
        int inbase = ((b * NZ + B0 * o0) * O + o1) * O + o2;
        const int tapstride = TS * O * O;
        float acc[5];
#pragma unroll
        for (int f = 0; f < 5; f++) {
            const float* p = g_bufB + OFF + f * FS + inbase;
            float a = 0.f;
#pragma unroll
            for (int t = 0; t < K; t++) a += p[t * tapstride];
            acc[f] = a;
        }
        float xm = acc[0] / numel;
        float ym = acc[1] / numel;
        float cross = acc[4] - ym * acc[0] - xm * acc[1] + ym * xm * numel;
        float xvar  = acc[2] - 2.f * xm * acc[0] + xm * xm * numel;
        float yvar  = acc[3] - 2.f * ym * acc[1] + ym * ym * numel;
        v = cross * cross / (xvar * yvar + 1e-5f);
    }
    __shared__ float wsum[8];
    int lane = threadIdx.x & 31;
    int wid  = threadIdx.x >> 5;
#pragma unroll
    for (int o = 16; o > 0; o >>= 1) v += __shfl_down_sync(0xffffffffu, v, o);
    if (lane == 0) wsum[wid] = v;
    __syncthreads();
    if (wid == 0) {
        v = (lane < 8) ? wsum[lane] : 0.f;
#pragma unroll
        for (int o = 4; o > 0; o >>= 1) v += __shfl_down_sync(0xffffffffu, v, o);
        if (lane == 0) g_partials[PBASE + blockIdx.x] = v;
    }
}

// ---------------------------------------------------------------------------
// Final combine: deterministic, fixed order.
// ---------------------------------------------------------------------------
__global__ void final_combine(float* __restrict__ out) {
    __shared__ float sh[256];
    const int   pbase[3] = {PBASE0, PBASE1, PBASE2};
    const int   nblk[3]  = {(N3_0 + 255) / 256, (N3_1 + 255) / 256, (N3_2 + 255) / 256};
    const float ninv[3]  = {1.0f / N3_0, 1.0f / N3_1, 1.0f / N3_2};
    const float wsc[3]   = {0.1f, 0.3f, 0.6f};
    float total = 0.f;
    for (int sc = 0; sc < 3; sc++) {
        float a = 0.f;
        for (int i = threadIdx.x; i < nblk[sc]; i += 256) a += g_partials[pbase[sc] + i];
        sh[threadIdx.x] = a;
        __syncthreads();
#pragma unroll
        for (int st = 128; st > 0; st >>= 1) {
            if (threadIdx.x < st) sh[threadIdx.x] += sh[threadIdx.x + st];
            __syncthreads();
        }
        if (threadIdx.x == 0) total += (1.0f - sh[0] * ninv[sc]) * wsc[sc];
        __syncthreads();
    }
    if (threadIdx.x == 0) out[0] = total;
}

// smem sizes per scale (zwin + xbuf + ybuf)
#define SMEM_F0 ((NZ0*5*O0 + 16*DIM) * (int)sizeof(float))   // 113,600 + 10,240
#define SMEM_F1 ((NZ1c*5*O1 + 16*DIM) * (int)sizeof(float))  //  80,000 + 10,240
#define SMEM_F2 ((NZ2*5*O2 + 16*DIM) * (int)sizeof(float))   //  14,400 + 10,240

extern "C" void kernel_launch(void* const* d_in, const int* in_sizes, int n_in,
                              void* d_out, int out_size) {
    const float* x = (const float*)d_in[0];
    const float* y = (const float*)d_in[1];
    float* out = (float*)d_out;

    // fused12 instantiations:
    //   scale0: K=10 S=2  O=71 NZ=80  ZS=2 idx = o + t
    //   scale1: K=20 S=5  O=25 NZ=160 ZS=1 idx = 5o + 2t
    //   scale2: K=40 S=10 O=9  NZ=80  ZS=2 idx = 5o + t
    cudaFuncSetAttribute(fused12<10, 2, O0, NZ0, 2, 1, 1, OFF0, FS0>,
                         cudaFuncAttributeMaxDynamicSharedMemorySize, SMEM_F0);
    cudaFuncSetAttribute(fused12<20, 5, O1, NZ1c, 1, 5, 2, OFF1, FS1>,
                         cudaFuncAttributeMaxDynamicSharedMemorySize, SMEM_F1);
    cudaFuncSetAttribute(fused12<40, 10, O2, NZ2, 2, 5, 1, OFF2, FS2>,
                         cudaFuncAttributeMaxDynamicSharedMemorySize, SMEM_F2);

    fused12<10, 2, O0, NZ0, 2, 1, 1, OFF0, FS0><<<NB * NZ0, 256, SMEM_F0>>>(x, y);
    pass34_k<10, O0, NZ0, 1, 1, OFF0, FS0, N3_0, PBASE0>
        <<<(N3_0 + 255) / 256, 256>>>();

    fused12<20, 5, O1, NZ1c, 1, 5, 2, OFF1, FS1><<<NB * NZ1c, 256, SMEM_F1>>>(x, y);
    pass34_k<20, O1, NZ1c, 5, 2, OFF1, FS1, N3_1, PBASE1>
        <<<(N3_1 + 255) / 256, 256>>>();

    fused12<40, 10, O2, NZ2, 2, 5, 1, OFF2, FS2><<<NB * NZ2, 256, SMEM_F2>>>(x, y);
    pass34_k<40, O2, NZ2, 5, 1, OFF2, FS2, N3_2, PBASE2>
        <<<(N3_2 + 255) / 256, 256>>>();

    final_combine<<<1, 256>>>(out);
}

// round 4
// speedup vs baseline: 2.5536x; 1.1143x over previous
#include <cuda_runtime.h>

#define DIM 160
#define NB  2

// ---- problem constants (img 160^3, >128 branch) ----
// scale0: k=10 s=2  O=71   scale1: k=20 s=5 O=25   scale2: k=40 s=10 O=9
// Parity pruning: scale0 taps touch only even z (NZ=80, z=2*zi, plane idx o+t)
//                 scale1 mixed parity (NZ=160, z=zi, plane idx 5*o+2t)
//                 scale2 even z only (NZ=80, z=2*zi, plane idx 5*o+t)
#define O0 71
#define O1 25
#define O2 9
#define NZ0 80
#define NZ1c 160
#define NZ2 80

#define FS0 (NB*NZ0*O0*O0)     // 806,560 per field
#define FS1 (NB*NZ1c*O1*O1)    // 200,000
#define FS2 (NB*NZ2*O2*O2)     //  12,960
#define OFF0 0
#define OFF1 (5*FS0)
#define OFF2 (OFF1 + 5*FS1)

#define N3_0 (NB*O0*O0*O0)     // 715,822
#define N3_1 (NB*O1*O1*O1)     //  31,250
#define N3_2 (NB*O2*O2*O2)     //   1,458

#define NBLK0 ((N3_0 + 255) / 256)   // 2797
#define NBLK1 ((N3_1 + 255) / 256)   //  123
#define NBLK2 ((N3_2 + 255) / 256)   //    6

#define PBASE0 0
#define PBASE1 2800
#define PBASE2 2928

__device__ float g_bufB[OFF2 + 5*FS2];   // ~20.4 MB
__device__ float g_partials[4096];

// ---------------------------------------------------------------------------
// fused12: pass1+pass2 for one scale, o2-chunked for occupancy.
// Block = (b, z0i, chunk). Phase 1: 8 warps stream z1 rows (coalesced LDG),
// compute 5 field products + z2-window sums for this o2 chunk into
// smem zwin[NZ][5][CH]. Phase 2: reduce z1 out of smem, write
// [f][b][z0i][o1][o2] to g_bufB.
// ---------------------------------------------------------------------------
template<int K, int S, int O, int NZ, int ZS, int B0, int TS, int OFF, int FS,
         int CH, int NCH>
__global__ __launch_bounds__(256) void fused12(const float* __restrict__ x,
                                               const float* __restrict__ y) {
    extern __shared__ float sm[];
    float* zwin = sm;                       // [NZ][5][CH]
    float* xb   = sm + NZ * 5 * CH;         // [8][DIM]
    float* yb   = xb + 8 * DIM;             // [8][DIM]

    int t2   = blockIdx.x;
    int ch   = t2 % NCH;  t2 /= NCH;
    int z0i  = t2 % NZ;
    int b    = t2 / NZ;
    int z0   = ZS * z0i;
    int obase = ch * CH;
    int cnt   = (obase + CH <= O) ? CH : (O - obase);

    int w    = threadIdx.x >> 5;
    int lane = threadIdx.x & 31;
    float* xrow = xb + w * DIM;
    float* yrow = yb + w * DIM;

    const int ROWS = NZ / 8;
    for (int r = 0; r < ROWS; r++) {
        int z1i = r * 8 + w;
        int z1  = ZS * z1i;
        const float* xr = x + ((size_t)(b * DIM + z0) * DIM + z1) * DIM;
        const float* yr = y + ((size_t)(b * DIM + z0) * DIM + z1) * DIM;
#pragma unroll
        for (int i = lane; i < DIM; i += 32) {
            xrow[i] = xr[i];
            yrow[i] = yr[i];
        }
        __syncwarp();
        for (int o2l = lane; o2l < cnt; o2l += 32) {
            int o2 = obase + o2l;
            float a0 = 0.f, a1 = 0.f, a2 = 0.f, a3 = 0.f, a4 = 0.f;
#pragma unroll
            for (int t = 0; t < K; t++) {
                int z2 = o2 * S + 2 * t;
                float xv = xrow[z2];
                float yv = yrow[z2];
                a0 += xv;
                a1 += yv;
                a2 += xv * xv;
                a3 += yv * yv;
                a4 += xv * yv;
            }
            float* zw = zwin + (size_t)z1i * 5 * CH + o2l;
            zw[0 * CH] = a0;
            zw[1 * CH] = a1;
            zw[2 * CH] = a2;
            zw[3 * CH] = a3;
            zw[4 * CH] = a4;
        }
        __syncwarp();
    }
    __syncthreads();

    const int ITEMS = 5 * O * CH;  // iterate full chunk; guard o2l < cnt
    for (int item = threadIdx.x; item < ITEMS; item += 256) {
        int f   = item / (O * CH);
        int rem = item % (O * CH);
        int o1  = rem / CH;
        int o2l = rem % CH;
        if (o2l >= cnt) continue;
        float acc = 0.f;
#pragma unroll
        for (int t = 0; t < K; t++)
            acc += zwin[(size_t)(B0 * o1 + TS * t) * 5 * CH + f * CH + o2l];
        g_bufB[OFF + f * FS + (((b * NZ) + z0i) * O + o1) * O + (obase + o2l)] = acc;
    }
}

// ---------------------------------------------------------------------------
// pass3+4 body: reduce z0 (compacted plane index), evaluate LNCC,
// deterministic block reduction into g_partials[PBASE + blk].
// ---------------------------------------------------------------------------
template<int K, int O, int NZ, int B0, int TS, int OFF, int FS, int N3, int PBASE>
__device__ __forceinline__ void pass34_body(int blk) {
    const float numel = (float)K * (float)K * (float)K;
    int idx = blk * 256 + threadIdx.x;
    float v = 0.f;
    if (idx < N3) {
        int o2 = idx % O;
        int r  = idx / O;
        int o1 = r % O;  r /= O;
        int o0 = r % O;
        int b  = r / O;
        int inbase = ((b * NZ + B0 * o0) * O + o1) * O + o2;
        const int tapstride = TS * O * O;
        float acc[5];
#pragma unroll
        for (int f = 0; f < 5; f++) {
            const float* p = g_bufB + OFF + f * FS + inbase;
            float a = 0.f;
#pragma unroll
            for (int t = 0; t < K; t++) a += p[t * tapstride];
            acc[f] = a;
        }
        float xm = acc[0] / numel;
        float ym = acc[1] / numel;
        float cross = acc[4] - ym * acc[0] - xm * acc[1] + ym * xm * numel;
        float xvar  = acc[2] - 2.f * xm * acc[0] + xm * xm * numel;
        float yvar  = acc[3] - 2.f * ym * acc[1] + ym * ym * numel;
        v = cross * cross / (xvar * yvar + 1e-5f);
    }
    __shared__ float wsum[8];
    int lane = threadIdx.x & 31;
    int wid  = threadIdx.x >> 5;
#pragma unroll
    for (int o = 16; o > 0; o >>= 1) v += __shfl_down_sync(0xffffffffu, v, o);
    if (lane == 0) wsum[wid] = v;
    __syncthreads();
    if (wid == 0) {
        v = (lane < 8) ? wsum[lane] : 0.f;
#pragma unroll
        for (int o = 4; o > 0; o >>= 1) v += __shfl_down_sync(0xffffffffu, v, o);
        if (lane == 0) g_partials[PBASE + blk] = v;
    }
}

// One launch covering all three scales.
__global__ __launch_bounds__(256) void pass34_all() {
    int b = blockIdx.x;
    if (b < NBLK0) {
        pass34_body<10, O0, NZ0, 1, 1, OFF0, FS0, N3_0, PBASE0>(b);
    } else if (b < NBLK0 + NBLK1) {
        pass34_body<20, O1, NZ1c, 5, 2, OFF1, FS1, N3_1, PBASE1>(b - NBLK0);
    } else {
        pass34_body<40, O2, NZ2, 5, 1, OFF2, FS2, N3_2, PBASE2>(b - NBLK0 - NBLK1);
    }
}

// ---------------------------------------------------------------------------
// Final combine: deterministic, fixed order.
// ---------------------------------------------------------------------------
__global__ void final_combine(float* __restrict__ out) {
    __shared__ float sh[256];
    const int   pbase[3] = {PBASE0, PBASE1, PBASE2};
    const int   nblk[3]  = {NBLK0, NBLK1, NBLK2};
    const float ninv[3]  = {1.0f / N3_0, 1.0f / N3_1, 1.0f / N3_2};
    const float wsc[3]   = {0.1f, 0.3f, 0.6f};
    float total = 0.f;
    for (int sc = 0; sc < 3; sc++) {
        float a = 0.f;
        for (int i = threadIdx.x; i < nblk[sc]; i += 256) a += g_partials[pbase[sc] + i];
        sh[threadIdx.x] = a;
        __syncthreads();
#pragma unroll
        for (int st = 128; st > 0; st >>= 1) {
            if (threadIdx.x < st) sh[threadIdx.x] += sh[threadIdx.x + st];
            __syncthreads();
        }
        if (threadIdx.x == 0) total += (1.0f - sh[0] * ninv[sc]) * wsc[sc];
        __syncthreads();
    }
    if (threadIdx.x == 0) out[0] = total;
}

// chunking: scale0 CH=36 NCH=2; scale1 CH=25 NCH=1; scale2 CH=9 NCH=1
#define SMEM_F0 ((NZ0*5*36 + 16*DIM) * (int)sizeof(float))   // 57,600 + 10,240
#define SMEM_F1 ((NZ1c*5*O1 + 16*DIM) * (int)sizeof(float))  // 80,000 + 10,240
#define SMEM_F2 ((NZ2*5*O2 + 16*DIM) * (int)sizeof(float))   // 14,400 + 10,240

extern "C" void kernel_launch(void* const* d_in, const int* in_sizes, int n_in,
                              void* d_out, int out_size) {
    const float* x = (const float*)d_in[0];
    const float* y = (const float*)d_in[1];
    float* out = (float*)d_out;

    cudaFuncSetAttribute(fused12<10, 2, O0, NZ0, 2, 1, 1, OFF0, FS0, 36, 2>,
                         cudaFuncAttributeMaxDynamicSharedMemorySize, SMEM_F0);
    cudaFuncSetAttribute(fused12<20, 5, O1, NZ1c, 1, 5, 2, OFF1, FS1, O1, 1>,
                         cudaFuncAttributeMaxDynamicSharedMemorySize, SMEM_F1);
    cudaFuncSetAttribute(fused12<40, 10, O2, NZ2, 2, 5, 1, OFF2, FS2, O2, 1>,
                         cudaFuncAttributeMaxDynamicSharedMemorySize, SMEM_F2);

    // Order: scale0 (even planes), scale2 (same even planes, L2-hot), scale1.
    fused12<10, 2, O0, NZ0, 2, 1, 1, OFF0, FS0, 36, 2>
        <<<NB * NZ0 * 2, 256, SMEM_F0>>>(x, y);
    fused12<40, 10, O2, NZ2, 2, 5, 1, OFF2, FS2, O2, 1>
        <<<NB * NZ2, 256, SMEM_F2>>>(x, y);
    fused12<20, 5, O1, NZ1c, 1, 5, 2, OFF1, FS1, O1, 1>
        <<<NB * NZ1c, 256, SMEM_F1>>>(x, y);

    pass34_all<<<NBLK0 + NBLK1 + NBLK2, 256>>>();
    final_combine<<<1, 256>>>(out);
}

// round 5
// speedup vs baseline: 2.7167x; 1.0638x over previous
#include <cuda_runtime.h>

#define DIM 160
#define NB  2

// scale0: k=10 s=2  O=71   scale1: k=20 s=5 O=25   scale2: k=40 s=10 O=9
// Parity pruning: sc0 even z only (NZ=80, plane idx o+t)
//                 sc1 mixed (NZ=160, plane idx 5o+2t)
//                 sc2 even z only (NZ=80, plane idx 5o+t)
#define O0 71
#define O1 25
#define O2 9
#define NZ0 80
#define NZ1c 160
#define NZ2 80

#define FS0 (NB*NZ0*O0*O0)
#define FS1 (NB*NZ1c*O1*O1)
#define FS2 (NB*NZ2*O2*O2)
#define OFF0 0
#define OFF1 (5*FS0)
#define OFF2 (OFF1 + 5*FS1)

#define N3_0 (NB*O0*O0*O0)     // 715,822
#define N3_1 (NB*O1*O1*O1)     //  31,250
#define N3_2 (NB*O2*O2*O2)     //   1,458

// pass34 block layout: sc0 strip-sliding, sc1/sc2 gather
#define NSTRIP0 4
#define STRIP0  18
#define NT0S   (NB*NSTRIP0*O0*O0)          // 40,328 threads
#define NBLK0S ((NT0S + 255) / 256)        // 158
#define NBLK1  ((N3_1 + 255) / 256)        // 123
#define NBLK2  ((N3_2 + 255) / 256)        //   6
#define TOTBLK (NBLK0S + NBLK1 + NBLK2)    // 287

#define PB0 0
#define PB1 192
#define PB2 320

__device__ float g_bufB[OFF2 + 5*FS2];   // ~20.4 MB
__device__ float g_partials[512];
__device__ unsigned int g_count = 0;

// fused grid: sc1 (heavy) first, then sc0, sc2
#define G1 (NB*NZ1c*2)    // 640  (CH=13, NCH=2)
#define G0 (NB*NZ0*2)     // 320  (CH=36, NCH=2)
#define G2 (NB*NZ2)       // 160  (CH=9,  NCH=1)
#define GALL (G1 + G0 + G2)

// ---------------------------------------------------------------------------
// fused12 body: pass1+pass2 for one scale, o2-chunked.
// ---------------------------------------------------------------------------
template<int K, int S, int O, int NZ, int ZS, int B0, int TS, int OFF, int FS,
         int CH, int NCH>
__device__ __forceinline__ void fused_body(int bid, const float* __restrict__ x,
                                           const float* __restrict__ y,
                                           float* sm) {
    float* zwin = sm;                       // [NZ][5][CH]
    float* xb   = sm + NZ * 5 * CH;         // [8][DIM]
    float* yb   = xb + 8 * DIM;             // [8][DIM]

    int ch   = bid % NCH;  bid /= NCH;
    int z0i  = bid % NZ;
    int b    = bid / NZ;
    int z0   = ZS * z0i;
    int obase = ch * CH;
    int cnt   = (obase + CH <= O) ? CH : (O - obase);

    int w    = threadIdx.x >> 5;
    int lane = threadIdx.x & 31;
    float* xrow = xb + w * DIM;
    float* yrow = yb + w * DIM;

    const int ROWS = NZ / 8;
    for (int r = 0; r < ROWS; r++) {
        int z1i = r * 8 + w;
        int z1  = ZS * z1i;
        const float* xr = x + ((size_t)(b * DIM + z0) * DIM + z1) * DIM;
        const float* yr = y + ((size_t)(b * DIM + z0) * DIM + z1) * DIM;
#pragma unroll
        for (int i = lane; i < DIM; i += 32) {
            xrow[i] = xr[i];
            yrow[i] = yr[i];
        }
        __syncwarp();
        for (int o2l = lane; o2l < cnt; o2l += 32) {
            int o2 = obase + o2l;
            float a0 = 0.f, a1 = 0.f, a2 = 0.f, a3 = 0.f, a4 = 0.f;
#pragma unroll
            for (int t = 0; t < K; t++) {
                int z2 = o2 * S + 2 * t;
                float xv = xrow[z2];
                float yv = yrow[z2];
                a0 += xv;
                a1 += yv;
                a2 += xv * xv;
                a3 += yv * yv;
                a4 += xv * yv;
            }
            float* zw = zwin + (size_t)z1i * 5 * CH + o2l;
            zw[0 * CH] = a0;
            zw[1 * CH] = a1;
            zw[2 * CH] = a2;
            zw[3 * CH] = a3;
            zw[4 * CH] = a4;
        }
        __syncwarp();
    }
    __syncthreads();

    const int ITEMS = 5 * O * CH;
    for (int item = threadIdx.x; item < ITEMS; item += 256) {
        int f   = item / (O * CH);
        int rem = item % (O * CH);
        int o1  = rem / CH;
        int o2l = rem % CH;
        if (o2l >= cnt) continue;
        float acc = 0.f;
#pragma unroll
        for (int t = 0; t < K; t++)
            acc += zwin[(size_t)(B0 * o1 + TS * t) * 5 * CH + f * CH + o2l];
        g_bufB[OFF + f * FS + (((b * NZ) + z0i) * O + o1) * O + (obase + o2l)] = acc;
    }
}

__global__ __launch_bounds__(256) void fused_all(const float* __restrict__ x,
                                                 const float* __restrict__ y) {
    extern __shared__ float sm[];
    int b = blockIdx.x;
    if (b < G1) {
        fused_body<20, 5, O1, NZ1c, 1, 5, 2, OFF1, FS1, 13, 2>(b, x, y, sm);
    } else if (b < G1 + G0) {
        fused_body<10, 2, O0, NZ0, 2, 1, 1, OFF0, FS0, 36, 2>(b - G1, x, y, sm);
    } else {
        fused_body<40, 10, O2, NZ2, 2, 5, 1, OFF2, FS2, 9, 1>(b - G1 - G0, x, y, sm);
    }
}

// ---------------------------------------------------------------------------
// LNCC from the 5 window sums
// ---------------------------------------------------------------------------
__device__ __forceinline__ float lncc_eval(float s0, float s1, float s2,
                                           float s3, float s4, float numel) {
    float xm = s0 / numel;
    float ym = s1 / numel;
    float cross = s4 - ym * s0 - xm * s1 + ym * xm * numel;
    float xvar  = s2 - 2.f * xm * s0 + xm * xm * numel;
    float yvar  = s3 - 2.f * ym * s1 + ym * ym * numel;
    return cross * cross / (xvar * yvar + 1e-5f);
}

// gather pass34 body (sc1, sc2): one output per thread
template<int K, int O, int NZ, int B0, int TS, int OFF, int FS, int N3>
__device__ __forceinline__ float pass34_gather(int blk) {
    const float numel = (float)K * (float)K * (float)K;
    int idx = blk * 256 + threadIdx.x;
    if (idx >= N3) return 0.f;
    int o2 = idx % O;
    int r  = idx / O;
    int o1 = r % O;  r /= O;
    int o0 = r % O;
    int b  = r / O;
    int inbase = ((b * NZ + B0 * o0) * O + o1) * O + o2;
    const int tapstride = TS * O * O;
    float acc[5];
#pragma unroll
    for (int f = 0; f < 5; f++) {
        const float* p = g_bufB + OFF + f * FS + inbase;
        float a = 0.f;
#pragma unroll
        for (int t = 0; t < K; t++) a += p[t * tapstride];
        acc[f] = a;
    }
    return lncc_eval(acc[0], acc[1], acc[2], acc[3], acc[4], numel);
}

// strip-sliding pass34 for sc0 (B0=1, TS=1, K=10): thread owns an o0-strip.
__device__ __forceinline__ float pass34_strip0(int blk) {
    int idx = blk * 256 + threadIdx.x;
    if (idx >= NT0S) return 0.f;
    int o2 = idx % O0;
    int r  = idx / O0;
    int o1 = r % O0;  r /= O0;
    int strip = r % NSTRIP0;
    int b     = r / NSTRIP0;
    int o0s = strip * STRIP0;
    int o0e = (o0s + STRIP0 < O0) ? o0s + STRIP0 : O0;   // 18,18,18,17
    const int PS = O0 * O0;
    int base = ((b * NZ0) * O0 + o1) * O0 + o2;          // z0i = 0 offset
    const float* p0 = g_bufB + OFF0 + base;
    float a0 = 0.f, a1 = 0.f, a2 = 0.f, a3 = 0.f, a4 = 0.f;
    float vsum = 0.f;
    for (int z = o0s; z < o0e + 9; z++) {
        int off = z * PS;
        a0 += p0[off];
        a1 += p0[off + 1 * FS0];
        a2 += p0[off + 2 * FS0];
        a3 += p0[off + 3 * FS0];
        a4 += p0[off + 4 * FS0];
        if (z >= o0s + 9) {
            vsum += lncc_eval(a0, a1, a2, a3, a4, 1000.0f);
            int offt = (z - 9) * PS;   // trailing plane (L1/L2-hot reload)
            a0 -= p0[offt];
            a1 -= p0[offt + 1 * FS0];
            a2 -= p0[offt + 2 * FS0];
            a3 -= p0[offt + 3 * FS0];
            a4 -= p0[offt + 4 * FS0];
        }
    }
    return vsum;
}

// ---------------------------------------------------------------------------
// pass34_all: all scales + last-block deterministic finalize.
// ---------------------------------------------------------------------------
__global__ __launch_bounds__(256) void pass34_all(float* __restrict__ out) {
    int bb = blockIdx.x;
    float v;
    int pslot;
    if (bb < NBLK0S) {
        v = pass34_strip0(bb);
        pslot = PB0 + bb;
    } else if (bb < NBLK0S + NBLK1) {
        v = pass34_gather<20, O1, NZ1c, 5, 2, OFF1, FS1, N3_1>(bb - NBLK0S);
        pslot = PB1 + (bb - NBLK0S);
    } else {
        v = pass34_gather<40, O2, NZ2, 5, 1, OFF2, FS2, N3_2>(bb - NBLK0S - NBLK1);
        pslot = PB2 + (bb - NBLK0S - NBLK1);
    }

    // deterministic block reduction
    __shared__ float wsum[8];
    int lane = threadIdx.x & 31;
    int wid  = threadIdx.x >> 5;
#pragma unroll
    for (int o = 16; o > 0; o >>= 1) v += __shfl_down_sync(0xffffffffu, v, o);
    if (lane == 0) wsum[wid] = v;
    __syncthreads();
    if (wid == 0) {
        v = (lane < 8) ? wsum[lane] : 0.f;
#pragma unroll
        for (int o = 4; o > 0; o >>= 1) v += __shfl_down_sync(0xffffffffu, v, o);
        if (lane == 0) g_partials[pslot] = v;
    }

    // last block finalizes (fixed-order sums -> deterministic)
    __shared__ bool isLast;
    __threadfence();
    if (threadIdx.x == 0) {
        unsigned int old = atomicAdd(&g_count, 1u);
        isLast = (old == TOTBLK - 1);
    }
    __syncthreads();
    if (!isLast) return;
    __threadfence();

    __shared__ float sh[256];
    const int   pbase[3] = {PB0, PB1, PB2};
    const int   nblk[3]  = {NBLK0S, NBLK1, NBLK2};
    const float ninv[3]  = {1.0f / N3_0, 1.0f / N3_1, 1.0f / N3_2};
    const float wsc[3]   = {0.1f, 0.3f, 0.6f};
    float total = 0.f;
    for (int sc = 0; sc < 3; sc++) {
        float a = 0.f;
        for (int i = threadIdx.x; i < nblk[sc]; i += 256) a += g_partials[pbase[sc] + i];
        sh[threadIdx.x] = a;
        __syncthreads();
#pragma unroll
        for (int st = 128; st > 0; st >>= 1) {
            if (threadIdx.x < st) sh[threadIdx.x] += sh[threadIdx.x + st];
            __syncthreads();
        }
        if (threadIdx.x == 0) total += (1.0f - sh[0] * ninv[sc]) * wsc[sc];
        __syncthreads();
    }
    if (threadIdx.x == 0) {
        out[0] = total;
        g_count = 0;   // reset for next graph replay
    }
}

// dynamic smem: max over scales = sc0 chunk: (80*5*36 + 16*160)*4 = 67,840 B
#define SMEM_ALL ((NZ0*5*36 + 16*DIM) * (int)sizeof(float))

extern "C" void kernel_launch(void* const* d_in, const int* in_sizes, int n_in,
                              void* d_out, int out_size) {
    const float* x = (const float*)d_in[0];
    const float* y = (const float*)d_in[1];
    float* out = (float*)d_out;

    cudaFuncSetAttribute(fused_all,
                         cudaFuncAttributeMaxDynamicSharedMemorySize, SMEM_ALL);

    fused_all<<<GALL, 256, SMEM_ALL>>>(x, y);
    pass34_all<<<TOTBLK, 256>>>(out);
}

// round 6
// speedup vs baseline: 2.8741x; 1.0580x over previous
#include <cuda_runtime.h>

#define DIM  160
#define DIMP 168   // padded row length in smem (bank spread, float4-aligned)
#define NB   2

// scale0: k=10 s=2  O=71   scale1: k=20 s=5 O=25   scale2: k=40 s=10 O=9
// Parity pruning: sc0/sc2 even z only (NZ=80), sc1 all z (NZ=160)
#define O0 71
#define O1 25
#define O2 9
#define NZ0 80
#define NZ1c 160
#define NZ2 80

#define FS0 (NB*NZ0*O0*O0)
#define FS1 (NB*NZ1c*O1*O1)
#define FS2 (NB*NZ2*O2*O2)
#define OFF0 0
#define OFF1 (5*FS0)
#define OFF2 (OFF1 + 5*FS1)

#define N3_0 (NB*O0*O0*O0)     // 715,822
#define N3_1 (NB*O1*O1*O1)     //  31,250
#define N3_2 (NB*O2*O2*O2)     //   1,458

// pass34 layout: sc0 strip-sliding (12 strips of 6), sc1/sc2 gather
#define NSTRIP0 12
#define STRIP0  6
#define NT0S   (NB*NSTRIP0*O0*O0)          // 120,984
#define NBLK0S ((NT0S + 255) / 256)        // 473
#define NBLK1  ((N3_1 + 255) / 256)        // 123
#define NBLK2  ((N3_2 + 255) / 256)        //   6
#define TOTBLK (NBLK0S + NBLK1 + NBLK2)    // 602

#define PB0 0
#define PB1 480
#define PB2 608

__device__ float g_bufB[OFF2 + 5*FS2];   // ~20.4 MB
__device__ float g_partials[768];
__device__ unsigned int g_count = 0;

// fused grid: sc1 first (heaviest per block), then merged sc0+sc2
#define G1  (NB*NZ1c)      // 320 (CH=25, NCH=1)
#define G02 (NB*NZ0*2)     // 320 (CH0=36, NCH=2)
#define GALL (G1 + G02)

// sc1 smem: zwin 160*5*25 + rows 2*8*168 = 22688 floats = 90,752 B (max)
#define SMEM_ALL ((NZ1c*5*O1 + 2*8*DIMP) * (int)sizeof(float))

// ---------------------------------------------------------------------------
// cooperative row-batch load: warp w loads row (rb + w) of both volumes
// into xb/yb[w][DIMP] via float4.
// ---------------------------------------------------------------------------
__device__ __forceinline__ void load_rows(const float* __restrict__ x,
                                          const float* __restrict__ y,
                                          float* xb, float* yb,
                                          int b, int z0, int z1,
                                          int w, int lane) {
    const float4* xr = (const float4*)(x + ((size_t)(b * DIM + z0) * DIM + z1) * DIM);
    const float4* yr = (const float4*)(y + ((size_t)(b * DIM + z0) * DIM + z1) * DIM);
    float4* xd = (float4*)(xb + w * DIMP);
    float4* yd = (float4*)(yb + w * DIMP);
#pragma unroll
    for (int i = lane; i < DIM / 4; i += 32) {
        xd[i] = xr[i];
        yd[i] = yr[i];
    }
}

// window sum of 5 field products over K taps from one smem row pair
template<int K, int S>
__device__ __forceinline__ void win5(const float* xr, const float* yr, int z2s,
                                     float* out, int stride) {
    float a0 = 0.f, a1 = 0.f, a2 = 0.f, a3 = 0.f, a4 = 0.f;
#pragma unroll
    for (int t = 0; t < K; t++) {
        float xv = xr[z2s + S * 0 + 2 * t];   // S only affects start; taps step 2
        float yv = yr[z2s + 2 * t];
        a0 += xv;
        a1 += yv;
        a2 += xv * xv;
        a3 += yv * yv;
        a4 += xv * yv;
    }
    out[0 * stride] = a0;
    out[1 * stride] = a1;
    out[2 * stride] = a2;
    out[3 * stride] = a3;
    out[4 * stride] = a4;
}

// ---------------------------------------------------------------------------
// sc1 body: K=20 S=5 O=25, NZ=160, ZS=1, full O (no chunking).
// zwin[160][5][25]; phase2 taps plane idx = 5*o1 + 2t.
// ---------------------------------------------------------------------------
__device__ __forceinline__ void body_sc1(int bid, const float* __restrict__ x,
                                         const float* __restrict__ y, float* sm) {
    const int K = 20, S = 5, O = O1, NZ = NZ1c;
    float* zwin = sm;                    // [NZ][5][O]
    float* xb = sm + NZ * 5 * O;
    float* yb = xb + 8 * DIMP;

    int z0i = bid % NZ;
    int b   = bid / NZ;
    int w    = threadIdx.x >> 5;
    int lane = threadIdx.x & 31;

    for (int rb = 0; rb < NZ; rb += 8) {
        load_rows(x, y, xb, yb, b, z0i, rb + w, w, lane);
        __syncthreads();
        for (int it = threadIdx.x; it < 8 * O; it += 256) {
            int rl  = it / O;
            int o2  = it % O;
            win5<K, 1>(xb + rl * DIMP, yb + rl * DIMP, o2 * S,
                       zwin + (size_t)(rb + rl) * 5 * O + o2, O);
        }
        __syncthreads();
    }

    const int ITEMS = 5 * O * O;
    for (int item = threadIdx.x; item < ITEMS; item += 256) {
        int f   = item / (O * O);
        int rem = item % (O * O);
        int o1  = rem / O;
        int o2  = rem % O;
        float acc = 0.f;
#pragma unroll
        for (int t = 0; t < K; t++)
            acc += zwin[(size_t)(5 * o1 + 2 * t) * 5 * O + f * O + o2];
        g_bufB[OFF1 + f * FS1 + (((b * NZ) + z0i) * O + o1) * O + o2] = acc;
    }
}

// ---------------------------------------------------------------------------
// merged sc0+sc2 body: even planes only. CH0=36, NCH=2.
// zwin0[80][5][CH0]; zwin2[80][5][9] (chunk 0 only).
// ---------------------------------------------------------------------------
#define CH0 36
__device__ __forceinline__ void body_sc02(int bid, const float* __restrict__ x,
                                          const float* __restrict__ y, float* sm) {
    const int NZ = 80;
    float* zwin0 = sm;                          // [80][5][CH0]
    float* zwin2 = sm + NZ * 5 * CH0;           // [80][5][9]
    float* xb    = zwin2 + NZ * 5 * O2;
    float* yb    = xb + 8 * DIMP;

    int ch  = bid & 1;  bid >>= 1;
    int z0i = bid % NZ;
    int b   = bid / NZ;
    int z0  = 2 * z0i;
    int obase = ch * CH0;                       // 0 or 36
    int w    = threadIdx.x >> 5;
    int lane = threadIdx.x & 31;

    for (int rb = 0; rb < NZ; rb += 8) {
        load_rows(x, y, xb, yb, b, z0, 2 * (rb + w), w, lane);
        __syncthreads();
        // sc0 windows for this chunk
        for (int it = threadIdx.x; it < 8 * CH0; it += 256) {
            int rl  = it / CH0;
            int o2l = it % CH0;
            int o2  = obase + o2l;
            if (o2 < O0)
                win5<10, 1>(xb + rl * DIMP, yb + rl * DIMP, o2 * 2,
                            zwin0 + (size_t)(rb + rl) * 5 * CH0 + o2l, CH0);
        }
        // sc2 windows (chunk 0 only)
        if (ch == 0) {
            for (int it = threadIdx.x; it < 8 * O2; it += 256) {
                int rl = it / O2;
                int o2 = it % O2;
                win5<40, 1>(xb + rl * DIMP, yb + rl * DIMP, o2 * 10,
                            zwin2 + (size_t)(rb + rl) * 5 * O2 + o2, O2);
            }
        }
        __syncthreads();
    }

    // phase2 sc0: plane idx = o1 + t
    {
        const int ITEMS = 5 * O0 * CH0;
        for (int item = threadIdx.x; item < ITEMS; item += 256) {
            int f   = item / (O0 * CH0);
            int rem = item % (O0 * CH0);
            int o1  = rem / CH0;
            int o2l = rem % CH0;
            int o2  = obase + o2l;
            if (o2 >= O0) continue;
            float acc = 0.f;
#pragma unroll
            for (int t = 0; t < 10; t++)
                acc += zwin0[(size_t)(o1 + t) * 5 * CH0 + f * CH0 + o2l];
            g_bufB[OFF0 + f * FS0 + (((b * NZ) + z0i) * O0 + o1) * O0 + o2] = acc;
        }
    }
    // phase2 sc2: plane idx = 5*o1 + t (chunk 0 only)
    if (ch == 0) {
        const int ITEMS = 5 * O2 * O2;
        for (int item = threadIdx.x; item < ITEMS; item += 256) {
            int f   = item / (O2 * O2);
            int rem = item % (O2 * O2);
            int o1  = rem / O2;
            int o2  = rem % O2;
            float acc = 0.f;
#pragma unroll
            for (int t = 0; t < 40; t++)
                acc += zwin2[(size_t)(5 * o1 + t) * 5 * O2 + f * O2 + o2];
            g_bufB[OFF2 + f * FS2 + (((b * NZ) + z0i) * O2 + o1) * O2 + o2] = acc;
        }
    }
}

__global__ __launch_bounds__(256) void fused_all(const float* __restrict__ x,
                                                 const float* __restrict__ y) {
    extern __shared__ float sm[];
    int b = blockIdx.x;
    if (b < G1) body_sc1(b, x, y, sm);
    else        body_sc02(b - G1, x, y, sm);
}

// ---------------------------------------------------------------------------
__device__ __forceinline__ float lncc_eval(float s0, float s1, float s2,
                                           float s3, float s4, float numel) {
    float xm = s0 / numel;
    float ym = s1 / numel;
    float cross = s4 - ym * s0 - xm * s1 + ym * xm * numel;
    float xvar  = s2 - 2.f * xm * s0 + xm * xm * numel;
    float yvar  = s3 - 2.f * ym * s1 + ym * ym * numel;
    return cross * cross / (xvar * yvar + 1e-5f);
}

template<int K, int O, int NZ, int B0, int TS, int OFF, int FS, int N3>
__device__ __forceinline__ float pass34_gather(int blk) {
    const float numel = (float)K * (float)K * (float)K;
    int idx = blk * 256 + threadIdx.x;
    if (idx >= N3) return 0.f;
    int o2 = idx % O;
    int r  = idx / O;
    int o1 = r % O;  r /= O;
    int o0 = r % O;
    int b  = r / O;
    int inbase = ((b * NZ + B0 * o0) * O + o1) * O + o2;
    const int tapstride = TS * O * O;
    float acc[5];
#pragma unroll
    for (int f = 0; f < 5; f++) {
        const float* p = g_bufB + OFF + f * FS + inbase;
        float a = 0.f;
#pragma unroll
        for (int t = 0; t < K; t++) a += p[t * tapstride];
        acc[f] = a;
    }
    return lncc_eval(acc[0], acc[1], acc[2], acc[3], acc[4], numel);
}

// sc0 strip-sliding: thread owns (b, strip, o1, o2); slides o0 over 6 outputs.
__device__ __forceinline__ float pass34_strip0(int blk) {
    int idx = blk * 256 + threadIdx.x;
    if (idx >= NT0S) return 0.f;
    int o2 = idx % O0;
    int r  = idx / O0;
    int o1 = r % O0;  r /= O0;
    int strip = r % NSTRIP0;
    int b     = r / NSTRIP0;
    int o0s = strip * STRIP0;
    int o0e = (o0s + STRIP0 < O0) ? o0s + STRIP0 : O0;
    const int PS = O0 * O0;
    int base = ((b * NZ0) * O0 + o1) * O0 + o2;
    const float* p0 = g_bufB + OFF0 + base;
    float a0 = 0.f, a1 = 0.f, a2 = 0.f, a3 = 0.f, a4 = 0.f;
    float vsum = 0.f;
    for (int z = o0s; z < o0e + 9; z++) {
        int off = z * PS;
        a0 += p0[off];
        a1 += p0[off + 1 * FS0];
        a2 += p0[off + 2 * FS0];
        a3 += p0[off + 3 * FS0];
        a4 += p0[off + 4 * FS0];
        if (z >= o0s + 9) {
            vsum += lncc_eval(a0, a1, a2, a3, a4, 1000.0f);
            int offt = (z - 9) * PS;
            a0 -= p0[offt];
            a1 -= p0[offt + 1 * FS0];
            a2 -= p0[offt + 2 * FS0];
            a3 -= p0[offt + 3 * FS0];
            a4 -= p0[offt + 4 * FS0];
        }
    }
    return vsum;
}

__global__ __launch_bounds__(256) void pass34_all(float* __restrict__ out) {
    int bb = blockIdx.x;
    float v;
    int pslot;
    if (bb < NBLK0S) {
        v = pass34_strip0(bb);
        pslot = PB0 + bb;
    } else if (bb < NBLK0S + NBLK1) {
        v = pass34_gather<20, O1, NZ1c, 5, 2, OFF1, FS1, N3_1>(bb - NBLK0S);
        pslot = PB1 + (bb - NBLK0S);
    } else {
        v = pass34_gather<40, O2, NZ2, 5, 1, OFF2, FS2, N3_2>(bb - NBLK0S - NBLK1);
        pslot = PB2 + (bb - NBLK0S - NBLK1);
    }

    __shared__ float wsum[8];
    int lane = threadIdx.x & 31;
    int wid  = threadIdx.x >> 5;
#pragma unroll
    for (int o = 16; o > 0; o >>= 1) v += __shfl_down_sync(0xffffffffu, v, o);
    if (lane == 0) wsum[wid] = v;
    __syncthreads();
    if (wid == 0) {
        v = (lane < 8) ? wsum[lane] : 0.f;
#pragma unroll
        for (int o = 4; o > 0; o >>= 1) v += __shfl_down_sync(0xffffffffu, v, o);
        if (lane == 0) g_partials[pslot] = v;
    }

    __shared__ bool isLast;
    __threadfence();
    if (threadIdx.x == 0) {
        unsigned int old = atomicAdd(&g_count, 1u);
        isLast = (old == TOTBLK - 1);
    }
    __syncthreads();
    if (!isLast) return;
    __threadfence();

    __shared__ float sh[256];
    const int   pbase[3] = {PB0, PB1, PB2};
    const int   nblk[3]  = {NBLK0S, NBLK1, NBLK2};
    const float ninv[3]  = {1.0f / N3_0, 1.0f / N3_1, 1.0f / N3_2};
    const float wsc[3]   = {0.1f, 0.3f, 0.6f};
    float total = 0.f;
    for (int sc = 0; sc < 3; sc++) {
        float a = 0.f;
        for (int i = threadIdx.x; i < nblk[sc]; i += 256) a += g_partials[pbase[sc] + i];
        sh[threadIdx.x] = a;
        __syncthreads();
#pragma unroll
        for (int st = 128; st > 0; st >>= 1) {
            if (threadIdx.x < st) sh[threadIdx.x] += sh[threadIdx.x + st];
            __syncthreads();
        }
        if (threadIdx.x == 0) total += (1.0f - sh[0] * ninv[sc]) * wsc[sc];
        __syncthreads();
    }
    if (threadIdx.x == 0) {
        out[0] = total;
        g_count = 0;
    }
}

extern "C" void kernel_launch(void* const* d_in, const int* in_sizes, int n_in,
                              void* d_out, int out_size) {
    const float* x = (const float*)d_in[0];
    const float* y = (const float*)d_in[1];
    float* out = (float*)d_out;

    cudaFuncSetAttribute(fused_all,
                         cudaFuncAttributeMaxDynamicSharedMemorySize, SMEM_ALL);

    fused_all<<<GALL, 256, SMEM_ALL>>>(x, y);
    pass34_all<<<TOTBLK, 256>>>(out);
}